// round 1
// baseline (speedup 1.0000x reference)
#include <cuda_runtime.h>
#include <cuda_fp16.h>
#include <math.h>

#define N 4096
#define LOG_SCALE 2.772588722239781f  // log(16)

// Scratch (allocation-free rule: __device__ globals)
__device__ __half  g_K [(size_t)N * N];   // 16*exp(-C/eps), row-major
__device__ __half  g_KT[(size_t)N * N];   // transpose of g_K
__device__ float4  g_a4[N];               // alpha transposed: a4[n] = alpha[0..3][n]
__device__ float4  g_b4[N];
__device__ float4  g_u4[N];               // scaling vectors (u' = u/16)
__device__ float4  g_v4[N];

// ---------------------------------------------------------------------------
// Precompute K = 16*exp(-C/eps) and its transpose (tiled smem transpose)
// ---------------------------------------------------------------------------
__global__ void exp_transpose_kernel(const float* __restrict__ C,
                                     const float* __restrict__ epsp) {
    __shared__ __half tile[32][33];
    const float inv_eps = 1.0f / *epsp;
    const int tx = threadIdx.x;          // 0..31
    const int ty = threadIdx.y;          // 0..7
    const int bx = blockIdx.x << 5;
    const int by = blockIdx.y << 5;

#pragma unroll
    for (int k = 0; k < 4; ++k) {
        int r = by + ty + (k << 3);
        float c = C[(size_t)r * N + bx + tx];
        __half h = __float2half_rn(__expf(LOG_SCALE - c * inv_eps));
        g_K[(size_t)r * N + bx + tx] = h;
        tile[ty + (k << 3)][tx] = h;
    }
    __syncthreads();
#pragma unroll
    for (int k = 0; k < 4; ++k) {
        int m = bx + ty + (k << 3);
        g_KT[(size_t)m * N + by + tx] = tile[tx][ty + (k << 3)];
    }
}

// ---------------------------------------------------------------------------
// Transpose alpha/beta to float4-per-column; init v = 1
// ---------------------------------------------------------------------------
__global__ void init_vecs_kernel(const float* __restrict__ alpha,
                                 const float* __restrict__ beta) {
    int n = blockIdx.x * 256 + threadIdx.x;
    if (n < N) {
        g_a4[n] = make_float4(alpha[n], alpha[N + n], alpha[2 * N + n], alpha[3 * N + n]);
        g_b4[n] = make_float4(beta[n],  beta[N + n],  beta[2 * N + n],  beta[3 * N + n]);
        g_v4[n] = make_float4(1.f, 1.f, 1.f, 1.f);
    }
}

// ---------------------------------------------------------------------------
// Batched GEMV + divide:  out4[row] = avec4[row] / (M[row,:] . vin4[:])
// M: fp16 row-major 4096x4096. vin4: float4 per column (S=4 batch).
// Block = 128 threads (4 warps), 4 rows per warp -> 16 rows/block, grid = 256.
// ---------------------------------------------------------------------------
#define FMA4(acc, s, v) \
    { acc.x = fmaf((s), (v).x, acc.x); acc.y = fmaf((s), (v).y, acc.y); \
      acc.z = fmaf((s), (v).z, acc.z); acc.w = fmaf((s), (v).w, acc.w); }

__global__ void __launch_bounds__(128, 2)
gemv_div_kernel(const __half* __restrict__ M,
                const float4* __restrict__ vin,
                const float4* __restrict__ avec,
                float4* __restrict__ vout) {
    extern __shared__ float4 sv[];   // 4096 float4 = 64KB

    // stage the dense vector batch into smem
    for (int i = threadIdx.x; i < N; i += 128) sv[i] = vin[i];
    __syncthreads();

    const int warp = threadIdx.x >> 5;
    const int lane = threadIdx.x & 31;
    const int row0 = (blockIdx.x << 4) + (warp << 2);

    const uint4* K0 = reinterpret_cast<const uint4*>(M + (size_t)(row0 + 0) * N);
    const uint4* K1 = reinterpret_cast<const uint4*>(M + (size_t)(row0 + 1) * N);
    const uint4* K2 = reinterpret_cast<const uint4*>(M + (size_t)(row0 + 2) * N);
    const uint4* K3 = reinterpret_cast<const uint4*>(M + (size_t)(row0 + 3) * N);

    float4 acc0 = make_float4(0.f, 0.f, 0.f, 0.f);
    float4 acc1 = acc0, acc2 = acc0, acc3 = acc0;

#pragma unroll 2
    for (int i = 0; i < 16; ++i) {
        const int c = (i << 5) + lane;          // uint4 index within row (0..511)
        uint4 k0 = K0[c], k1 = K1[c], k2 = K2[c], k3 = K3[c];
        const float4* vv = sv + (c << 3);       // 8 columns worth of v

#pragma unroll
        for (int p = 0; p < 4; ++p) {
            float2 f0 = __half22float2(reinterpret_cast<const __half2*>(&k0)[p]);
            float2 f1 = __half22float2(reinterpret_cast<const __half2*>(&k1)[p]);
            float2 f2 = __half22float2(reinterpret_cast<const __half2*>(&k2)[p]);
            float2 f3 = __half22float2(reinterpret_cast<const __half2*>(&k3)[p]);
            float4 va = vv[2 * p];
            float4 vb = vv[2 * p + 1];
            FMA4(acc0, f0.x, va); FMA4(acc0, f0.y, vb);
            FMA4(acc1, f1.x, va); FMA4(acc1, f1.y, vb);
            FMA4(acc2, f2.x, va); FMA4(acc2, f2.y, vb);
            FMA4(acc3, f3.x, va); FMA4(acc3, f3.y, vb);
        }
    }

    // butterfly-reduce 16 partials across the warp
    float vals[16];
    vals[0]  = acc0.x; vals[1]  = acc0.y; vals[2]  = acc0.z; vals[3]  = acc0.w;
    vals[4]  = acc1.x; vals[5]  = acc1.y; vals[6]  = acc1.z; vals[7]  = acc1.w;
    vals[8]  = acc2.x; vals[9]  = acc2.y; vals[10] = acc2.z; vals[11] = acc2.w;
    vals[12] = acc3.x; vals[13] = acc3.y; vals[14] = acc3.z; vals[15] = acc3.w;
#pragma unroll
    for (int off = 16; off > 0; off >>= 1) {
#pragma unroll
        for (int j = 0; j < 16; ++j)
            vals[j] += __shfl_xor_sync(0xffffffffu, vals[j], off);
    }

    if (lane < 4) {
        int row = row0 + lane;
        float4 y = make_float4(vals[lane * 4 + 0], vals[lane * 4 + 1],
                               vals[lane * 4 + 2], vals[lane * 4 + 3]);
        float4 a = avec[row];
        vout[row] = make_float4(a.x / y.x, a.y / y.y, a.z / y.z, a.w / y.w);
    }
}

// ---------------------------------------------------------------------------
// f = eps*(log u' + log 16), g = eps*log v ; layout: f[(s,n)] then g[(s,n)]
// ---------------------------------------------------------------------------
__global__ void finalize_kernel(float* __restrict__ out,
                                const float* __restrict__ epsp) {
    int n = blockIdx.x * 256 + threadIdx.x;
    if (n >= N) return;
    const float eps = *epsp;
    float4 u = g_u4[n];
    float4 v = g_v4[n];
    out[0 * N + n] = eps * (logf(u.x) + LOG_SCALE);
    out[1 * N + n] = eps * (logf(u.y) + LOG_SCALE);
    out[2 * N + n] = eps * (logf(u.z) + LOG_SCALE);
    out[3 * N + n] = eps * (logf(u.w) + LOG_SCALE);
    float* og = out + 4 * N;
    og[0 * N + n] = eps * logf(v.x);
    og[1 * N + n] = eps * logf(v.y);
    og[2 * N + n] = eps * logf(v.z);
    og[3 * N + n] = eps * logf(v.w);
}

// ---------------------------------------------------------------------------
extern "C" void kernel_launch(void* const* d_in, const int* in_sizes, int n_in,
                              void* d_out, int out_size) {
    const float* alpha = (const float*)d_in[0];
    const float* beta  = (const float*)d_in[1];
    const float* C     = (const float*)d_in[2];
    const float* eps   = (const float*)d_in[3];
    float* out = (float*)d_out;

    cudaFuncSetAttribute(gemv_div_kernel,
                         cudaFuncAttributeMaxDynamicSharedMemorySize, 65536);

    __half  *pK, *pKT;
    float4  *pA, *pB, *pU, *pV;
    cudaGetSymbolAddress((void**)&pK,  g_K);
    cudaGetSymbolAddress((void**)&pKT, g_KT);
    cudaGetSymbolAddress((void**)&pA,  g_a4);
    cudaGetSymbolAddress((void**)&pB,  g_b4);
    cudaGetSymbolAddress((void**)&pU,  g_u4);
    cudaGetSymbolAddress((void**)&pV,  g_v4);

    exp_transpose_kernel<<<dim3(128, 128), dim3(32, 8)>>>(C, eps);
    init_vecs_kernel<<<16, 256>>>(alpha, beta);

    for (int it = 0; it < 10; ++it) {
        gemv_div_kernel<<<256, 128, 65536>>>(pK,  pV, pA, pU);  // u = a/(K v)
        gemv_div_kernel<<<256, 128, 65536>>>(pKT, pU, pB, pV);  // v = b/(KT u)
    }

    finalize_kernel<<<16, 256>>>(out, eps);
}

// round 2
// speedup vs baseline: 1.1343x; 1.1343x over previous
#include <cuda_runtime.h>
#include <cuda_fp16.h>
#include <math.h>

#define N 4096
#define LOG_SCALE 2.772588722239781f  // log(16)
#define SPLIT 4
#define CPB (N / SPLIT)               // 1024 columns per block
#define RPB 16                        // rows per block (4 warps x 4 rows)
#define ROW_TILES (N / RPB)           // 256

// Scratch (allocation-free rule: __device__ globals)
__device__ __half  g_K [(size_t)N * N];   // 16*exp(-C/eps), row-major
__device__ __half  g_KT[(size_t)N * N];   // transpose
__device__ float4  g_a4[N];               // alpha transposed (S=4 per column)
__device__ float4  g_b4[N];
__device__ float4  g_u4[N];               // u' = u/16
__device__ float4  g_v4[N];
__device__ float4  g_pu[SPLIT * N];       // partial dot products
__device__ float4  g_pv[SPLIT * N];

// ---------------------------------------------------------------------------
// Blackwell packed f32x2 helpers
// ---------------------------------------------------------------------------
__device__ __forceinline__ unsigned long long ffma2(unsigned long long s,
                                                    unsigned long long v,
                                                    unsigned long long acc) {
    unsigned long long r;
    asm("fma.rn.f32x2 %0, %1, %2, %3;" : "=l"(r) : "l"(s), "l"(v), "l"(acc));
    return r;
}
__device__ __forceinline__ unsigned long long pack2(float s) {
    unsigned u = __float_as_uint(s);
    unsigned long long r;
    asm("mov.b64 %0, {%1, %1};" : "=l"(r) : "r"(u));
    return r;
}
__device__ __forceinline__ float2 unpack2(unsigned long long p) {
    unsigned lo, hi;
    asm("mov.b64 {%0, %1}, %2;" : "=r"(lo), "=r"(hi) : "l"(p));
    return make_float2(__uint_as_float(lo), __uint_as_float(hi));
}

// ---------------------------------------------------------------------------
// Precompute K = 16*exp(-C/eps) and its transpose
// ---------------------------------------------------------------------------
__global__ void exp_transpose_kernel(const float* __restrict__ C,
                                     const float* __restrict__ epsp) {
    __shared__ __half tile[32][33];
    const float inv_eps = 1.0f / *epsp;
    const int tx = threadIdx.x, ty = threadIdx.y;
    const int bx = blockIdx.x << 5, by = blockIdx.y << 5;

#pragma unroll
    for (int k = 0; k < 4; ++k) {
        int r = by + ty + (k << 3);
        float c = C[(size_t)r * N + bx + tx];
        __half h = __float2half_rn(__expf(LOG_SCALE - c * inv_eps));
        g_K[(size_t)r * N + bx + tx] = h;
        tile[ty + (k << 3)][tx] = h;
    }
    __syncthreads();
#pragma unroll
    for (int k = 0; k < 4; ++k) {
        int m = bx + ty + (k << 3);
        g_KT[(size_t)m * N + by + tx] = tile[tx][ty + (k << 3)];
    }
}

// ---------------------------------------------------------------------------
__global__ void init_vecs_kernel(const float* __restrict__ alpha,
                                 const float* __restrict__ beta) {
    int n = blockIdx.x * 256 + threadIdx.x;
    if (n < N) {
        g_a4[n] = make_float4(alpha[n], alpha[N + n], alpha[2 * N + n], alpha[3 * N + n]);
        g_b4[n] = make_float4(beta[n],  beta[N + n],  beta[2 * N + n],  beta[3 * N + n]);
        g_v4[n] = make_float4(1.f, 1.f, 1.f, 1.f);
    }
}

// ---------------------------------------------------------------------------
// Partial batched GEMV: block (rowTile, chunk) computes, for 16 rows,
//   pout[chunk*N + row] = sum over cols [chunk*CPB, (chunk+1)*CPB) of M[row,c]*vin[c]
// 128 threads = 4 warps x 4 rows. No smem, no syncthreads.
// ---------------------------------------------------------------------------
__global__ void __launch_bounds__(128)
gemv_part_kernel(const __half* __restrict__ M,
                 const float4* __restrict__ vin,
                 float* __restrict__ pout) {
    const int warp = threadIdx.x >> 5;
    const int lane = threadIdx.x & 31;
    const int row0 = blockIdx.x * RPB + (warp << 2);
    const size_t colBase = (size_t)blockIdx.y * CPB;

    const uint4* K0 = reinterpret_cast<const uint4*>(M + (size_t)(row0 + 0) * N + colBase);
    const uint4* K1 = reinterpret_cast<const uint4*>(M + (size_t)(row0 + 1) * N + colBase);
    const uint4* K2 = reinterpret_cast<const uint4*>(M + (size_t)(row0 + 2) * N + colBase);
    const uint4* K3 = reinterpret_cast<const uint4*>(M + (size_t)(row0 + 3) * N + colBase);
    const ulonglong2* vv = reinterpret_cast<const ulonglong2*>(vin + colBase);

    unsigned long long acc[4][2];
#pragma unroll
    for (int r = 0; r < 4; ++r) { acc[r][0] = 0ull; acc[r][1] = 0ull; }

#pragma unroll 2
    for (int i = 0; i < CPB / 256; ++i) {     // 4 iterations
        const int c = (i << 5) + lane;        // uint4 index (8 halves)
        uint4 k0 = K0[c], k1 = K1[c], k2 = K2[c], k3 = K3[c];
        const ulonglong2* vp = vv + ((size_t)c << 3);  // 8 float4 per uint4

#pragma unroll
        for (int p = 0; p < 4; ++p) {
            ulonglong2 va = vp[2 * p];
            ulonglong2 vb = vp[2 * p + 1];
            float2 f0 = __half22float2(reinterpret_cast<const __half2*>(&k0)[p]);
            float2 f1 = __half22float2(reinterpret_cast<const __half2*>(&k1)[p]);
            float2 f2 = __half22float2(reinterpret_cast<const __half2*>(&k2)[p]);
            float2 f3 = __half22float2(reinterpret_cast<const __half2*>(&k3)[p]);

            unsigned long long s;
            s = pack2(f0.x); acc[0][0] = ffma2(s, va.x, acc[0][0]); acc[0][1] = ffma2(s, va.y, acc[0][1]);
            s = pack2(f0.y); acc[0][0] = ffma2(s, vb.x, acc[0][0]); acc[0][1] = ffma2(s, vb.y, acc[0][1]);
            s = pack2(f1.x); acc[1][0] = ffma2(s, va.x, acc[1][0]); acc[1][1] = ffma2(s, va.y, acc[1][1]);
            s = pack2(f1.y); acc[1][0] = ffma2(s, vb.x, acc[1][0]); acc[1][1] = ffma2(s, vb.y, acc[1][1]);
            s = pack2(f2.x); acc[2][0] = ffma2(s, va.x, acc[2][0]); acc[2][1] = ffma2(s, va.y, acc[2][1]);
            s = pack2(f2.y); acc[2][0] = ffma2(s, vb.x, acc[2][0]); acc[2][1] = ffma2(s, vb.y, acc[2][1]);
            s = pack2(f3.x); acc[3][0] = ffma2(s, va.x, acc[3][0]); acc[3][1] = ffma2(s, va.y, acc[3][1]);
            s = pack2(f3.y); acc[3][0] = ffma2(s, vb.x, acc[3][0]); acc[3][1] = ffma2(s, vb.y, acc[3][1]);
        }
    }

    // vals[j], j = r*4 + s_component
    float vals[16];
#pragma unroll
    for (int r = 0; r < 4; ++r) {
        float2 lo = unpack2(acc[r][0]);
        float2 hi = unpack2(acc[r][1]);
        vals[r * 4 + 0] = lo.x; vals[r * 4 + 1] = lo.y;
        vals[r * 4 + 2] = hi.x; vals[r * 4 + 3] = hi.y;
    }

    // Stage 0: fold lanes across bit0 (all 16 values)
#pragma unroll
    for (int j = 0; j < 16; ++j)
        vals[j] += __shfl_xor_sync(0xffffffffu, vals[j], 1);

    // Halving tree over offsets 2,4,8,16: 16 -> 1 values per lane
    int m = 16;
#pragma unroll
    for (int off = 2; off <= 16; off <<= 1) {
        m >>= 1;
        bool upper = (lane & off) != 0;
#pragma unroll
        for (int j = 0; j < 8; ++j) {
            if (j < m) {
                float send = upper ? vals[j] : vals[j + m];
                float recv = __shfl_xor_sync(0xffffffffu, send, off);
                vals[j] = (upper ? vals[j + m] : vals[j]) + recv;
            }
        }
    }

    // lane (with bit0 == 0) holds j = f(lane bits 1..4)
    if ((lane & 1) == 0) {
        int j = ((lane & 2)  ? 8 : 0) | ((lane & 4)  ? 4 : 0)
              | ((lane & 8)  ? 2 : 0) | ((lane & 16) ? 1 : 0);
        int r = j >> 2;
        int s = j & 3;
        pout[((size_t)blockIdx.y * N + row0 + r) * 4 + s] = vals[0];
    }
}

// ---------------------------------------------------------------------------
// out[n] = num[n] / sum_k p[k][n]
// ---------------------------------------------------------------------------
__global__ void reduce_div_kernel(const float4* __restrict__ num,
                                  const float4* __restrict__ p,
                                  float4* __restrict__ out) {
    int n = blockIdx.x * 256 + threadIdx.x;
    if (n >= N) return;
    float4 s = p[n];
#pragma unroll
    for (int k = 1; k < SPLIT; ++k) {
        float4 q = p[k * N + n];
        s.x += q.x; s.y += q.y; s.z += q.z; s.w += q.w;
    }
    float4 a = num[n];
    out[n] = make_float4(a.x / s.x, a.y / s.y, a.z / s.z, a.w / s.w);
}

// ---------------------------------------------------------------------------
// f = eps*(log u' + log 16), g = eps*log v
// ---------------------------------------------------------------------------
__global__ void finalize_kernel(float* __restrict__ out,
                                const float* __restrict__ epsp) {
    int n = blockIdx.x * 256 + threadIdx.x;
    if (n >= N) return;
    const float eps = *epsp;
    float4 u = g_u4[n];
    float4 v = g_v4[n];
    out[0 * N + n] = eps * (logf(u.x) + LOG_SCALE);
    out[1 * N + n] = eps * (logf(u.y) + LOG_SCALE);
    out[2 * N + n] = eps * (logf(u.z) + LOG_SCALE);
    out[3 * N + n] = eps * (logf(u.w) + LOG_SCALE);
    float* og = out + 4 * N;
    og[0 * N + n] = eps * logf(v.x);
    og[1 * N + n] = eps * logf(v.y);
    og[2 * N + n] = eps * logf(v.z);
    og[3 * N + n] = eps * logf(v.w);
}

// ---------------------------------------------------------------------------
extern "C" void kernel_launch(void* const* d_in, const int* in_sizes, int n_in,
                              void* d_out, int out_size) {
    const float* alpha = (const float*)d_in[0];
    const float* beta  = (const float*)d_in[1];
    const float* C     = (const float*)d_in[2];
    const float* eps   = (const float*)d_in[3];
    float* out = (float*)d_out;

    __half *pK, *pKT;
    float4 *pA, *pB, *pU, *pV, *pPU, *pPV;
    cudaGetSymbolAddress((void**)&pK,  g_K);
    cudaGetSymbolAddress((void**)&pKT, g_KT);
    cudaGetSymbolAddress((void**)&pA,  g_a4);
    cudaGetSymbolAddress((void**)&pB,  g_b4);
    cudaGetSymbolAddress((void**)&pU,  g_u4);
    cudaGetSymbolAddress((void**)&pV,  g_v4);
    cudaGetSymbolAddress((void**)&pPU, g_pu);
    cudaGetSymbolAddress((void**)&pPV, g_pv);

    exp_transpose_kernel<<<dim3(128, 128), dim3(32, 8)>>>(C, eps);
    init_vecs_kernel<<<16, 256>>>(alpha, beta);

    dim3 ggrid(ROW_TILES, SPLIT);
    for (int it = 0; it < 10; ++it) {
        gemv_part_kernel<<<ggrid, 128>>>(pK,  pV, (float*)pPU);   // partials of K v
        reduce_div_kernel<<<16, 256>>>(pA, pPU, pU);              // u = a / (K v)
        gemv_part_kernel<<<ggrid, 128>>>(pKT, pU, (float*)pPV);   // partials of K^T u
        reduce_div_kernel<<<16, 256>>>(pB, pPV, pV);              // v = b / (K^T u)
    }

    finalize_kernel<<<16, 256>>>(out, eps);
}

// round 3
// speedup vs baseline: 2.1005x; 1.8518x over previous
#include <cuda_runtime.h>
#include <cuda_fp16.h>
#include <math.h>

#define N 4096
#define LOG_SCALE 2.772588722239781f  // log(16)
#define NBLOCKS 256
#define NTHREADS 128
#define NITER 10

// Scratch (allocation-free rule: __device__ globals)
__device__ __half  g_K [(size_t)N * N];   // 16*exp(-C/eps), row-major
__device__ __half  g_KT[(size_t)N * N];   // transpose
__device__ float4  g_u4[N];               // u' = u/16 (S=4 packed per column)
__device__ float4  g_v4[N];
__device__ unsigned long long g_count;    // grid-barrier generation counter

// ---------------------------------------------------------------------------
// Blackwell packed f32x2 helpers
// ---------------------------------------------------------------------------
__device__ __forceinline__ unsigned long long ffma2(unsigned long long s,
                                                    unsigned long long v,
                                                    unsigned long long acc) {
    unsigned long long r;
    asm("fma.rn.f32x2 %0, %1, %2, %3;" : "=l"(r) : "l"(s), "l"(v), "l"(acc));
    return r;
}
__device__ __forceinline__ unsigned long long pack2(float s) {
    unsigned u = __float_as_uint(s);
    unsigned long long r;
    asm("mov.b64 %0, {%1, %1};" : "=l"(r) : "r"(u));
    return r;
}
__device__ __forceinline__ float2 unpack2(unsigned long long p) {
    unsigned lo, hi;
    asm("mov.b64 {%0, %1}, %2;" : "=r"(lo), "=r"(hi) : "l"(p));
    return make_float2(__uint_as_float(lo), __uint_as_float(hi));
}

// ---------------------------------------------------------------------------
// Software grid barrier: monotonic generation counter (replay-safe).
// Release-arrive after bar.sync; acquire-spin; bar.sync to fan out.
// ---------------------------------------------------------------------------
__device__ __forceinline__ void grid_sync() {
    __syncthreads();
    if (threadIdx.x == 0) {
        unsigned long long gen;
        asm volatile("atom.add.release.gpu.u64 %0, [%1], 1;"
                     : "=l"(gen) : "l"(&g_count) : "memory");
        unsigned long long target =
            (gen / NBLOCKS + 1ull) * (unsigned long long)NBLOCKS;
        unsigned long long cur;
        do {
            asm volatile("ld.acquire.gpu.u64 %0, [%1];"
                         : "=l"(cur) : "l"(&g_count) : "memory");
        } while (cur < target);
    }
    __syncthreads();
}

// ---------------------------------------------------------------------------
// Precompute K = 16*exp(-C/eps) and its transpose
// ---------------------------------------------------------------------------
__global__ void exp_transpose_kernel(const float* __restrict__ C,
                                     const float* __restrict__ epsp) {
    __shared__ __half tile[32][33];
    const float inv_eps = 1.0f / *epsp;
    const int tx = threadIdx.x, ty = threadIdx.y;
    const int bx = blockIdx.x << 5, by = blockIdx.y << 5;

#pragma unroll
    for (int k = 0; k < 4; ++k) {
        int r = by + ty + (k << 3);
        float c = C[(size_t)r * N + bx + tx];
        __half h = __float2half_rn(__expf(LOG_SCALE - c * inv_eps));
        g_K[(size_t)r * N + bx + tx] = h;
        tile[ty + (k << 3)][tx] = h;
    }
    __syncthreads();
#pragma unroll
    for (int k = 0; k < 4; ++k) {
        int m = bx + ty + (k << 3);
        g_KT[(size_t)m * N + by + tx] = tile[tx][ty + (k << 3)];
    }
}

// ---------------------------------------------------------------------------
// Persistent Sinkhorn loop. 256 blocks x 128 threads (co-residency guaranteed:
// 72KB smem -> 3 blocks/SM >= 2 needed). Each warp: 4 rows, full 4096 cols.
// v staged in smem with 9-stride padding (lane stride 144B -> conflict-free).
// ---------------------------------------------------------------------------
__global__ void __launch_bounds__(NTHREADS)
sinkhorn_persistent_kernel(const float* __restrict__ alpha,
                           const float* __restrict__ beta,
                           const float* __restrict__ epsp,
                           float* __restrict__ out) {
    extern __shared__ float4 sv[];   // 512 groups * 9 float4 = 73728 B

    const int tid  = threadIdx.x;
    const int warp = tid >> 5;
    const int lane = tid & 31;
    const int row0 = blockIdx.x * 16 + (warp << 2);

    for (int it = 0; it < 2 * NITER; ++it) {
        const __half* M        = (it & 1) ? g_KT : g_K;
        const float4* vin      = (it & 1) ? g_u4 : g_v4;
        float*        vout     = (float*)((it & 1) ? g_v4 : g_u4);
        const float*  numsrc   = (it & 1) ? beta  : alpha;

        // stage vector into padded smem (L2 reads: L1 is stale across barrier)
        if (it == 0) {
            for (int i = tid; i < N; i += NTHREADS)
                sv[(i >> 3) * 9 + (i & 7)] = make_float4(1.f, 1.f, 1.f, 1.f);
        } else {
            for (int i = tid; i < N; i += NTHREADS)
                sv[(i >> 3) * 9 + (i & 7)] = __ldcg(vin + i);
        }
        __syncthreads();

        const uint4* K0 = reinterpret_cast<const uint4*>(M + (size_t)(row0 + 0) * N);
        const uint4* K1 = reinterpret_cast<const uint4*>(M + (size_t)(row0 + 1) * N);
        const uint4* K2 = reinterpret_cast<const uint4*>(M + (size_t)(row0 + 2) * N);
        const uint4* K3 = reinterpret_cast<const uint4*>(M + (size_t)(row0 + 3) * N);

        unsigned long long acc[4][2];
#pragma unroll
        for (int r = 0; r < 4; ++r) { acc[r][0] = 0ull; acc[r][1] = 0ull; }

#pragma unroll 2
        for (int i = 0; i < 16; ++i) {            // 512 uint4 per row / 32 lanes
            const int c = (i << 5) + lane;        // col-group index (8 halves)
            uint4 k0 = K0[c], k1 = K1[c], k2 = K2[c], k3 = K3[c];
            const ulonglong2* vp = reinterpret_cast<const ulonglong2*>(sv + c * 9);

#pragma unroll
            for (int p = 0; p < 4; ++p) {
                ulonglong2 va = vp[2 * p];
                ulonglong2 vb = vp[2 * p + 1];
                float2 f0 = __half22float2(reinterpret_cast<const __half2*>(&k0)[p]);
                float2 f1 = __half22float2(reinterpret_cast<const __half2*>(&k1)[p]);
                float2 f2 = __half22float2(reinterpret_cast<const __half2*>(&k2)[p]);
                float2 f3 = __half22float2(reinterpret_cast<const __half2*>(&k3)[p]);

                unsigned long long s;
                s = pack2(f0.x); acc[0][0] = ffma2(s, va.x, acc[0][0]); acc[0][1] = ffma2(s, va.y, acc[0][1]);
                s = pack2(f0.y); acc[0][0] = ffma2(s, vb.x, acc[0][0]); acc[0][1] = ffma2(s, vb.y, acc[0][1]);
                s = pack2(f1.x); acc[1][0] = ffma2(s, va.x, acc[1][0]); acc[1][1] = ffma2(s, va.y, acc[1][1]);
                s = pack2(f1.y); acc[1][0] = ffma2(s, vb.x, acc[1][0]); acc[1][1] = ffma2(s, vb.y, acc[1][1]);
                s = pack2(f2.x); acc[2][0] = ffma2(s, va.x, acc[2][0]); acc[2][1] = ffma2(s, va.y, acc[2][1]);
                s = pack2(f2.y); acc[2][0] = ffma2(s, vb.x, acc[2][0]); acc[2][1] = ffma2(s, vb.y, acc[2][1]);
                s = pack2(f3.x); acc[3][0] = ffma2(s, va.x, acc[3][0]); acc[3][1] = ffma2(s, va.y, acc[3][1]);
                s = pack2(f3.y); acc[3][0] = ffma2(s, vb.x, acc[3][0]); acc[3][1] = ffma2(s, vb.y, acc[3][1]);
            }
        }

        // vals[j], j = r*4 + s_component
        float vals[16];
#pragma unroll
        for (int r = 0; r < 4; ++r) {
            float2 lo = unpack2(acc[r][0]);
            float2 hi = unpack2(acc[r][1]);
            vals[r * 4 + 0] = lo.x; vals[r * 4 + 1] = lo.y;
            vals[r * 4 + 2] = hi.x; vals[r * 4 + 3] = hi.y;
        }

        // Stage 0: fold across bit0 (all 16 values)
#pragma unroll
        for (int j = 0; j < 16; ++j)
            vals[j] += __shfl_xor_sync(0xffffffffu, vals[j], 1);

        // Halving tree over offsets 2,4,8,16
        int m = 16;
#pragma unroll
        for (int off = 2; off <= 16; off <<= 1) {
            m >>= 1;
            bool upper = (lane & off) != 0;
#pragma unroll
            for (int j = 0; j < 8; ++j) {
                if (j < m) {
                    float send = upper ? vals[j] : vals[j + m];
                    float recv = __shfl_xor_sync(0xffffffffu, send, off);
                    vals[j] = (upper ? vals[j + m] : vals[j]) + recv;
                }
            }
        }

        // epilogue: lane(bit0==0) holds j = f(lane bits 1..4); fused divide
        if ((lane & 1) == 0) {
            int j = ((lane & 2)  ? 8 : 0) | ((lane & 4)  ? 4 : 0)
                  | ((lane & 8)  ? 2 : 0) | ((lane & 16) ? 1 : 0);
            int r = j >> 2;
            int s = j & 3;
            int row = row0 + r;
            float a = __ldg(numsrc + (size_t)s * N + row);
            __stcg(vout + (size_t)row * 4 + s, a / vals[0]);
        }

        grid_sync();
    }

    // finalize: f = eps*(log u' + log16), g = eps*log v
    int gtid = blockIdx.x * NTHREADS + tid;
    if (gtid < N) {
        const float eps = *epsp;
        float4 u = __ldcg(g_u4 + gtid);
        float4 v = __ldcg(g_v4 + gtid);
        out[0 * N + gtid] = eps * (logf(u.x) + LOG_SCALE);
        out[1 * N + gtid] = eps * (logf(u.y) + LOG_SCALE);
        out[2 * N + gtid] = eps * (logf(u.z) + LOG_SCALE);
        out[3 * N + gtid] = eps * (logf(u.w) + LOG_SCALE);
        float* og = out + 4 * N;
        og[0 * N + gtid] = eps * logf(v.x);
        og[1 * N + gtid] = eps * logf(v.y);
        og[2 * N + gtid] = eps * logf(v.z);
        og[3 * N + gtid] = eps * logf(v.w);
    }
}

// ---------------------------------------------------------------------------
extern "C" void kernel_launch(void* const* d_in, const int* in_sizes, int n_in,
                              void* d_out, int out_size) {
    const float* alpha = (const float*)d_in[0];
    const float* beta  = (const float*)d_in[1];
    const float* C     = (const float*)d_in[2];
    const float* eps   = (const float*)d_in[3];
    float* out = (float*)d_out;

    static int configured = 0;
    if (!configured) {
        cudaFuncSetAttribute(sinkhorn_persistent_kernel,
                             cudaFuncAttributeMaxDynamicSharedMemorySize, 73728);
        configured = 1;
    }

    exp_transpose_kernel<<<dim3(128, 128), dim3(32, 8)>>>(C, eps);
    sinkhorn_persistent_kernel<<<NBLOCKS, NTHREADS, 73728>>>(alpha, beta, eps, out);
}

// round 4
// speedup vs baseline: 2.5530x; 1.2154x over previous
#include <cuda_runtime.h>
#include <cuda_fp16.h>
#include <math.h>

#define N 4096
#define LOG_SCALE 2.772588722239781f  // log(16)
#define NBLOCKS 256
#define NTHREADS 256
#define NITER 10
#define CPB 2048                      // columns per block (2-way split)
#define GROUPS (CPB / 8)              // 256 uint4 groups per block
#define SMEM_BYTES (GROUPS * 9 * 16)  // 36864 B (9-stride padded float4)

// Scratch (allocation-free rule: __device__ globals)
__device__ __half  g_K [(size_t)N * N];   // 16*exp(-C/eps), row-major
__device__ __half  g_KT[(size_t)N * N];   // transpose
__device__ float   g_pu[2 * N * 4];       // u-direction partials [chunk][row][s]
__device__ float   g_pv[2 * N * 4];       // v-direction partials
__device__ unsigned long long g_count;    // grid-barrier generation counter

// ---------------------------------------------------------------------------
// Blackwell packed f32x2 helpers
// ---------------------------------------------------------------------------
__device__ __forceinline__ unsigned long long ffma2(unsigned long long s,
                                                    unsigned long long v,
                                                    unsigned long long acc) {
    unsigned long long r;
    asm("fma.rn.f32x2 %0, %1, %2, %3;" : "=l"(r) : "l"(s), "l"(v), "l"(acc));
    return r;
}
__device__ __forceinline__ unsigned long long pack2(float s) {
    unsigned u = __float_as_uint(s);
    unsigned long long r;
    asm("mov.b64 %0, {%1, %1};" : "=l"(r) : "r"(u));
    return r;
}
__device__ __forceinline__ float2 unpack2(unsigned long long p) {
    unsigned lo, hi;
    asm("mov.b64 {%0, %1}, %2;" : "=r"(lo), "=r"(hi) : "l"(p));
    return make_float2(__uint_as_float(lo), __uint_as_float(hi));
}

// ---------------------------------------------------------------------------
// Software grid barrier: monotonic generation counter (graph-replay safe)
// ---------------------------------------------------------------------------
__device__ __forceinline__ void grid_sync() {
    __syncthreads();
    if (threadIdx.x == 0) {
        unsigned long long gen;
        asm volatile("atom.add.release.gpu.u64 %0, [%1], 1;"
                     : "=l"(gen) : "l"(&g_count) : "memory");
        unsigned long long target =
            (gen / NBLOCKS + 1ull) * (unsigned long long)NBLOCKS;
        unsigned long long cur;
        do {
            asm volatile("ld.acquire.gpu.u64 %0, [%1];"
                         : "=l"(cur) : "l"(&g_count) : "memory");
        } while (cur < target);
    }
    __syncthreads();
}

// ---------------------------------------------------------------------------
// Precompute K = 16*exp(-C/eps) and its transpose
// ---------------------------------------------------------------------------
__global__ void exp_transpose_kernel(const float* __restrict__ C,
                                     const float* __restrict__ epsp) {
    __shared__ __half tile[32][33];
    const float inv_eps = 1.0f / *epsp;
    const int tx = threadIdx.x, ty = threadIdx.y;
    const int bx = blockIdx.x << 5, by = blockIdx.y << 5;

#pragma unroll
    for (int k = 0; k < 4; ++k) {
        int r = by + ty + (k << 3);
        float c = C[(size_t)r * N + bx + tx];
        __half h = __float2half_rn(__expf(LOG_SCALE - c * inv_eps));
        g_K[(size_t)r * N + bx + tx] = h;
        tile[ty + (k << 3)][tx] = h;
    }
    __syncthreads();
#pragma unroll
    for (int k = 0; k < 4; ++k) {
        int m = bx + ty + (k << 3);
        g_KT[(size_t)m * N + by + tx] = tile[tx][ty + (k << 3)];
    }
}

// ---------------------------------------------------------------------------
// Persistent Sinkhorn. 256 blocks x 256 threads (8 warps), block = 32 rows x
// 2048 cols (blockIdx = rowTile*2 + chunk). Each warp: 4 rows, 2048 cols.
// Division fused into staging: sv[c] = num[c] / (p0[c] + p1[c]).
// ---------------------------------------------------------------------------
__global__ void __launch_bounds__(NTHREADS, 2)
sinkhorn_persistent_kernel(const float* __restrict__ alpha,
                           const float* __restrict__ beta,
                           const float* __restrict__ epsp,
                           float* __restrict__ out) {
    extern __shared__ float4 sv[];   // GROUPS * 9 float4 = 36864 B

    const int tid   = threadIdx.x;
    const int warp  = tid >> 5;
    const int lane  = tid & 31;
    const int rowT  = blockIdx.x >> 1;
    const int chunk = blockIdx.x & 1;
    const int row0  = rowT * 32 + (warp << 2);
    const size_t colBase = (size_t)chunk * CPB;

    for (int it = 0; it < 2 * NITER; ++it) {
        const __half* M    = (it & 1) ? g_KT : g_K;
        float*        pout = (it & 1) ? g_pv : g_pu;

        // ---- stage input vector (divide fused here) ----
        if (it == 0) {
            for (int i = tid; i < CPB; i += NTHREADS)
                sv[(i >> 3) * 9 + (i & 7)] = make_float4(1.f, 1.f, 1.f, 1.f);
        } else {
            const float*  num  = (it & 1) ? alpha : beta;   // numerator of previous half-iter
            const float4* part = (const float4*)((it & 1) ? g_pu : g_pv);
            for (int i = tid; i < CPB; i += NTHREADS) {
                int col = (int)colBase + i;
                float4 p0 = __ldcg(part + col);
                float4 p1 = __ldcg(part + N + col);
                float4 r;
                r.x = __fdividef(__ldg(num + 0 * N + col), p0.x + p1.x);
                r.y = __fdividef(__ldg(num + 1 * N + col), p0.y + p1.y);
                r.z = __fdividef(__ldg(num + 2 * N + col), p0.z + p1.z);
                r.w = __fdividef(__ldg(num + 3 * N + col), p0.w + p1.w);
                sv[(i >> 3) * 9 + (i & 7)] = r;
            }
        }
        __syncthreads();

        const uint4* K0 = reinterpret_cast<const uint4*>(M + (size_t)(row0 + 0) * N + colBase);
        const uint4* K1 = reinterpret_cast<const uint4*>(M + (size_t)(row0 + 1) * N + colBase);
        const uint4* K2 = reinterpret_cast<const uint4*>(M + (size_t)(row0 + 2) * N + colBase);
        const uint4* K3 = reinterpret_cast<const uint4*>(M + (size_t)(row0 + 3) * N + colBase);

        unsigned long long acc[4][2];
#pragma unroll
        for (int r = 0; r < 4; ++r) { acc[r][0] = 0ull; acc[r][1] = 0ull; }

#pragma unroll 2
        for (int i = 0; i < GROUPS / 32; ++i) {   // 8 iterations
            const int c = (i << 5) + lane;        // local uint4-group (8 halves)
            uint4 k0 = K0[c], k1 = K1[c], k2 = K2[c], k3 = K3[c];
            const ulonglong2* vp = reinterpret_cast<const ulonglong2*>(sv + c * 9);

#pragma unroll
            for (int p = 0; p < 4; ++p) {
                ulonglong2 va = vp[2 * p];
                ulonglong2 vb = vp[2 * p + 1];
                float2 f0 = __half22float2(reinterpret_cast<const __half2*>(&k0)[p]);
                float2 f1 = __half22float2(reinterpret_cast<const __half2*>(&k1)[p]);
                float2 f2 = __half22float2(reinterpret_cast<const __half2*>(&k2)[p]);
                float2 f3 = __half22float2(reinterpret_cast<const __half2*>(&k3)[p]);

                unsigned long long s;
                s = pack2(f0.x); acc[0][0] = ffma2(s, va.x, acc[0][0]); acc[0][1] = ffma2(s, va.y, acc[0][1]);
                s = pack2(f0.y); acc[0][0] = ffma2(s, vb.x, acc[0][0]); acc[0][1] = ffma2(s, vb.y, acc[0][1]);
                s = pack2(f1.x); acc[1][0] = ffma2(s, va.x, acc[1][0]); acc[1][1] = ffma2(s, va.y, acc[1][1]);
                s = pack2(f1.y); acc[1][0] = ffma2(s, vb.x, acc[1][0]); acc[1][1] = ffma2(s, vb.y, acc[1][1]);
                s = pack2(f2.x); acc[2][0] = ffma2(s, va.x, acc[2][0]); acc[2][1] = ffma2(s, va.y, acc[2][1]);
                s = pack2(f2.y); acc[2][0] = ffma2(s, vb.x, acc[2][0]); acc[2][1] = ffma2(s, vb.y, acc[2][1]);
                s = pack2(f3.x); acc[3][0] = ffma2(s, va.x, acc[3][0]); acc[3][1] = ffma2(s, va.y, acc[3][1]);
                s = pack2(f3.y); acc[3][0] = ffma2(s, vb.x, acc[3][0]); acc[3][1] = ffma2(s, vb.y, acc[3][1]);
            }
        }

        // vals[j], j = r*4 + s_component
        float vals[16];
#pragma unroll
        for (int r = 0; r < 4; ++r) {
            float2 lo = unpack2(acc[r][0]);
            float2 hi = unpack2(acc[r][1]);
            vals[r * 4 + 0] = lo.x; vals[r * 4 + 1] = lo.y;
            vals[r * 4 + 2] = hi.x; vals[r * 4 + 3] = hi.y;
        }

        // fold across bit0, then halving tree over offsets 2,4,8,16
#pragma unroll
        for (int j = 0; j < 16; ++j)
            vals[j] += __shfl_xor_sync(0xffffffffu, vals[j], 1);
        int m = 16;
#pragma unroll
        for (int off = 2; off <= 16; off <<= 1) {
            m >>= 1;
            bool upper = (lane & off) != 0;
#pragma unroll
            for (int j = 0; j < 8; ++j) {
                if (j < m) {
                    float send = upper ? vals[j] : vals[j + m];
                    float recv = __shfl_xor_sync(0xffffffffu, send, off);
                    vals[j] = (upper ? vals[j + m] : vals[j]) + recv;
                }
            }
        }

        // write raw partial dot products (no divide here)
        if ((lane & 1) == 0) {
            int j = ((lane & 2)  ? 8 : 0) | ((lane & 4)  ? 4 : 0)
                  | ((lane & 8)  ? 2 : 0) | ((lane & 16) ? 1 : 0);
            int r = j >> 2;
            int s = j & 3;
            __stcg(pout + (size_t)chunk * N * 4 + (size_t)(row0 + r) * 4 + s, vals[0]);
        }

        grid_sync();
    }

    // finalize: u = a/(pu0+pu1), v = b/(pv0+pv1); f = eps*(log u + log16), g = eps*log v
    int n = blockIdx.x * NTHREADS + tid;
    if (n < N) {
        const float eps = *epsp;
        const float4* pu = (const float4*)g_pu;
        const float4* pv = (const float4*)g_pv;
        float4 s0 = __ldcg(pu + n), s1 = __ldcg(pu + N + n);
        float4 t0 = __ldcg(pv + n), t1 = __ldcg(pv + N + n);
        out[0 * N + n] = eps * (logf(__fdividef(alpha[0 * N + n], s0.x + s1.x)) + LOG_SCALE);
        out[1 * N + n] = eps * (logf(__fdividef(alpha[1 * N + n], s0.y + s1.y)) + LOG_SCALE);
        out[2 * N + n] = eps * (logf(__fdividef(alpha[2 * N + n], s0.z + s1.z)) + LOG_SCALE);
        out[3 * N + n] = eps * (logf(__fdividef(alpha[3 * N + n], s0.w + s1.w)) + LOG_SCALE);
        float* og = out + 4 * N;
        og[0 * N + n] = eps * logf(__fdividef(beta[0 * N + n], t0.x + t1.x));
        og[1 * N + n] = eps * logf(__fdividef(beta[1 * N + n], t0.y + t1.y));
        og[2 * N + n] = eps * logf(__fdividef(beta[2 * N + n], t0.z + t1.z));
        og[3 * N + n] = eps * logf(__fdividef(beta[3 * N + n], t0.w + t1.w));
    }
}

// ---------------------------------------------------------------------------
extern "C" void kernel_launch(void* const* d_in, const int* in_sizes, int n_in,
                              void* d_out, int out_size) {
    const float* alpha = (const float*)d_in[0];
    const float* beta  = (const float*)d_in[1];
    const float* C     = (const float*)d_in[2];
    const float* eps   = (const float*)d_in[3];
    float* out = (float*)d_out;

    cudaFuncSetAttribute(sinkhorn_persistent_kernel,
                         cudaFuncAttributeMaxDynamicSharedMemorySize, SMEM_BYTES);

    exp_transpose_kernel<<<dim3(128, 128), dim3(32, 8)>>>(C, eps);
    sinkhorn_persistent_kernel<<<NBLOCKS, NTHREADS, SMEM_BYTES>>>(alpha, beta, eps, out);
}